// round 4
// baseline (speedup 1.0000x reference)
#include <cuda_runtime.h>
#include <cuda_fp16.h>
#include <cstdint>

#define B_  4
#define LQ  512
#define LK  512
#define DQ  256
#define DC  256
#define H_  128

typedef unsigned long long ull;

// Scratch (__device__ globals: allocation-free rule)
__device__ __half g_qph [B_ * LQ * H_];       // [row][h] : query proj + bq (fp16)
__device__ __half g_c2h [B_ * H_ * LK];       // [b][h][k]: 2*(ctx proj + bc) (fp16)
__device__ float  g_attn[B_ * LQ * LK];       // softmax weights
__device__ ull    g_WT2 [2][DQ / 2][H_];      // [m][d2][h] = pk(W[h][2d2], W[h][2d2+1])

// ---------- f32x2 helpers ----------
__device__ __forceinline__ ull pk(float a, float b) {
    ull r; asm("mov.b64 %0, {%1, %2};" : "=l"(r) : "f"(a), "f"(b)); return r;
}
__device__ __forceinline__ void upk(ull v, float& a, float& b) {
    asm("mov.b64 {%0, %1}, %2;" : "=f"(a), "=f"(b) : "l"(v));
}
__device__ __forceinline__ ull fma2(ull a, ull b, ull c) {
    ull r; asm("fma.rn.f32x2 %0, %1, %2, %3;" : "=l"(r) : "l"(a), "l"(b), "l"(c)); return r;
}
__device__ __forceinline__ __half2 tanh2(__half2 v) {
    uint32_t x = *reinterpret_cast<uint32_t*>(&v), y;
    asm("tanh.approx.f16x2 %0, %1;" : "=r"(y) : "r"(x));
    return *reinterpret_cast<__half2*>(&y);
}

// ---------------------------------------------------------------------------
// Kernel 0: pack-transpose W -> g_WT2[m][d2][h]
// ---------------------------------------------------------------------------
__global__ __launch_bounds__(256) void wt_kernel(
    const float* __restrict__ Wq, const float* __restrict__ Wc)
{
    const int m = blockIdx.y;
    const float* W = m ? Wc : Wq;
    const int idx = blockIdx.x * 256 + threadIdx.x;   // 0..16383
    const int d2 = idx >> 7, h = idx & 127;
    g_WT2[m][d2][h] = pk(W[h * DQ + 2 * d2], W[h * DQ + 2 * d2 + 1]);
}

// ---------------------------------------------------------------------------
// Kernel 1: projections, FFMA2, lane-coalesced W via WT2; fp16 outputs.
// ---------------------------------------------------------------------------
__global__ __launch_bounds__(256) void proj_kernel(
    const float* __restrict__ query, const float* __restrict__ context,
    const float* __restrict__ bq, const float* __restrict__ bc)
{
    __shared__ float insh[16][256];                  // 16 KB input tile

    const int m    = blockIdx.x >> 7;                // 0=query, 1=context
    const int tile = blockIdx.x & 127;
    const float* in   = m ? context : query;
    const float* bias = m ? bc : bq;
    const int t  = threadIdx.x;
    const int r0 = tile * 16;

    {   // coalesced coop load 16x256
        const float4* src = (const float4*)(in + (size_t)r0 * 256);
        float4* dst = (float4*)insh;
        #pragma unroll
        for (int i = t; i < 16 * 64; i += 256) dst[i] = src[i];
    }
    __syncthreads();

    const int h  = t & 127;
    const int rg = t >> 7;                           // rows rg*8 .. rg*8+7
    const float bb = bias[h];
    ull acc[8];
    #pragma unroll
    for (int j = 0; j < 8; j++) acc[j] = pk(bb, 0.0f);

    const ull* wp = &g_WT2[m][0][h];                 // stride H_ per d2
    #pragma unroll 4
    for (int d4 = 0; d4 < 64; d4++) {
        const ull w01 = wp[(2 * d4)     * H_];       // coalesced LDG.64 over h
        const ull w23 = wp[(2 * d4 + 1) * H_];
        #pragma unroll
        for (int j = 0; j < 8; j++) {
            const ulonglong2 q2 = *(const ulonglong2*)&insh[rg * 8 + j][d4 * 4];
            acc[j] = fma2(w01, q2.x, acc[j]);
            acc[j] = fma2(w23, q2.y, acc[j]);
        }
    }

    #pragma unroll
    for (int j = 0; j < 8; j++) {
        float lo, hi; upk(acc[j], lo, hi);
        const float s = lo + hi;
        const int row = r0 + rg * 8 + j;
        if (m == 0) {
            g_qph[(size_t)row * H_ + h] = __float2half(s);
        } else {
            const int b = row >> 9, k = row & 511;
            g_c2h[((size_t)b * H_ + h) * LK + k] = __float2half(2.0f * s);
        }
    }
}

// ---------------------------------------------------------------------------
// Kernel 2: scores + softmax. 1024 CTAs (b, 2q) -> ~55 warps/SM (the R1
// occupancy that hit the MUFU floor), now with the f16x2 tanh (2 tanh/MUFU).
// Thread: kt = t&127 -> k = 4kt..4kt+3 via ONE LDG.64 of fp16; q = t>>7.
// Per h: 1 LDG + 2 HADD2 + 2 MUFU-tanh2 + 4 F2F + 2 FFMA2  (MUFU-bound).
// ---------------------------------------------------------------------------
__global__ __launch_bounds__(256) void scores_kernel(const float* __restrict__ Wv)
{
    __shared__ __half2 qsh[2][H_];    // (qp, qp) per (q, h)
    __shared__ ull     wv2[H_];       // (Wv, Wv) f32x2
    __shared__ float   sc[2][LK];     // 4 KB scores

    const int tile = blockIdx.x;          // 0..1023
    const int b  = tile >> 8;             // 256 tiles per batch
    const int q0 = (tile & 255) * 2;
    const int t  = threadIdx.x;

    if (t < 2 * H_) {
        const int q = t >> 7, h = t & 127;
        qsh[q][h] = __half2half2(g_qph[((size_t)(b * LQ + q0 + q)) * H_ + h]);
    }
    if (t < H_) { const float w = Wv[t]; wv2[t] = pk(w, w); }
    __syncthreads();

    const int kt = t & 127;               // k-quad index
    const int q  = t >> 7;                // 0 or 1
    const ull* cp8 = (const ull*)(g_c2h + (size_t)b * H_ * LK) + kt; // 128 ull/row

    ull acc0 = 0ULL, acc1 = 0ULL;         // f32x2 accumulators (k01, k23)

    #pragma unroll 4
    for (int h = 0; h < H_; h++) {
        const ull cc = cp8[(size_t)h * 128];       // LDG.64: 4 fp16 k-values
        const __half2 c01 = ((const __half2*)&cc)[0];
        const __half2 c23 = ((const __half2*)&cc)[1];
        const __half2 qq = qsh[q][h];              // broadcast LDS
        const __half2 t01 = tanh2(__hadd2(qq, c01));
        const __half2 t23 = tanh2(__hadd2(qq, c23));
        const float2 f01 = __half22float2(t01);
        const float2 f23 = __half22float2(t23);
        const ull wv = wv2[h];                     // broadcast LDS
        acc0 = fma2(pk(f01.x, f01.y), wv, acc0);
        acc1 = fma2(pk(f23.x, f23.y), wv, acc1);
    }

    {
        float s0, s1, s2, s3;
        upk(acc0, s0, s1); upk(acc1, s2, s3);
        *(float4*)&sc[q][kt * 4] = make_float4(s0, s1, s2, s3);
    }
    __syncthreads();

    // softmax: warp w handles q = q0 + w  (w in {0,1}); other warps exit
    const int w = t >> 5, lane = t & 31;
    if (w < 2) {
        float e[16];
        float mx = -1e30f;
        #pragma unroll
        for (int j = 0; j < 16; j++) {
            e[j] = sc[w][lane + j * 32];
            mx = fmaxf(mx, e[j]);
        }
        #pragma unroll
        for (int off = 16; off > 0; off >>= 1)
            mx = fmaxf(mx, __shfl_xor_sync(0xffffffffu, mx, off));
        float s = 0.0f;
        #pragma unroll
        for (int j = 0; j < 16; j++) { e[j] = __expf(e[j] - mx); s += e[j]; }
        #pragma unroll
        for (int off = 16; off > 0; off >>= 1)
            s += __shfl_xor_sync(0xffffffffu, s, off);
        const float inv = 1.0f / s;
        float* dst = g_attn + ((size_t)b * LQ + q0 + w) * LK;
        #pragma unroll
        for (int j = 0; j < 16; j++) dst[lane + j * 32] = e[j] * inv;
    }
}

// ---------------------------------------------------------------------------
// Kernel 3: out = attn @ context — smem GEMM, BM=64(q) BN=32(d) BK=32(k).
// 256 CTAs = 4b x 8qt x 8dt (fills all 148 SMs). 256 threads, 2q x 4d each.
// ---------------------------------------------------------------------------
__global__ __launch_bounds__(256) void out_kernel(
    const float* __restrict__ context, float* __restrict__ out)
{
    __shared__ float a_sh[32][68];    // [k][q] transposed attn tile (pad)
    __shared__ float c_sh[32][36];    // [k][d] ctx tile (pad)

    const int bx = blockIdx.x;        // 0..255
    const int b  = bx >> 6;
    const int q0 = ((bx >> 3) & 7) * 64;
    const int d0 = (bx & 7) * 32;
    const int t  = threadIdx.x;

    // global load coords
    const int aq = t >> 2, af = t & 3;      // attn: row aq (64), f4 cols af, af+4
    const int cr = t >> 3, cf = t & 7;      // ctx:  row cr (32), f4 col cf

    const float4* ag = (const float4*)(g_attn + ((size_t)b * LQ + q0) * LK); // 128 f4/row
    const float4* cg = (const float4*)(context + (size_t)b * LK * DC + d0);  // 64 f4/row

    // prefetch stage 0
    float4 pa0 = ag[(size_t)aq * 128 + af];
    float4 pa1 = ag[(size_t)aq * 128 + af + 4];
    float4 pc0 = cg[(size_t)cr * 64 + cf];

    const int tx = t & 7;             // d = d0 + tx*4
    const int ty = t >> 3;            // q-pair = q0 + ty*2
    ull acc[4];
    acc[0] = acc[1] = acc[2] = acc[3] = 0ULL;

    #pragma unroll 1
    for (int s = 0; s < 16; s++) {
        __syncthreads();
        // attn -> smem transposed [k][q]
        a_sh[af * 4 + 0][aq] = pa0.x;
        a_sh[af * 4 + 1][aq] = pa0.y;
        a_sh[af * 4 + 2][aq] = pa0.z;
        a_sh[af * 4 + 3][aq] = pa0.w;
        a_sh[(af + 4) * 4 + 0][aq] = pa1.x;
        a_sh[(af + 4) * 4 + 1][aq] = pa1.y;
        a_sh[(af + 4) * 4 + 2][aq] = pa1.z;
        a_sh[(af + 4) * 4 + 3][aq] = pa1.w;
        // ctx -> smem direct [k][d]
        *(float4*)&c_sh[cr][cf * 4] = pc0;
        __syncthreads();

        if (s < 15) {   // prefetch next stage (overlaps compute)
            const int k4 = (s + 1) * 8;
            const int kr = (s + 1) * 32;
            pa0 = ag[(size_t)aq * 128 + k4 + af];
            pa1 = ag[(size_t)aq * 128 + k4 + af + 4];
            pc0 = cg[(size_t)(kr + cr) * 64 + cf];
        }

        #pragma unroll
        for (int k = 0; k < 32; k++) {
            const ull a2 = *(const ull*)&a_sh[k][ty * 2];   // (q0, q1) pair
            const float4 c4 = *(const float4*)&c_sh[k][tx * 4];
            acc[0] = fma2(a2, pk(c4.x, c4.x), acc[0]);
            acc[1] = fma2(a2, pk(c4.y, c4.y), acc[1]);
            acc[2] = fma2(a2, pk(c4.z, c4.z), acc[2]);
            acc[3] = fma2(a2, pk(c4.w, c4.w), acc[3]);
        }
    }

    float o[2][4];
    #pragma unroll
    for (int d = 0; d < 4; d++) upk(acc[d], o[0][d], o[1][d]);

    #pragma unroll
    for (int qi = 0; qi < 2; qi++) {
        float4* dst = (float4*)(out + ((size_t)b * LQ + q0 + ty * 2 + qi) * DC
                                + d0 + tx * 4);
        *dst = make_float4(o[qi][0], o[qi][1], o[qi][2], o[qi][3]);
    }
}

// ---------------------------------------------------------------------------
extern "C" void kernel_launch(void* const* d_in, const int* in_sizes, int n_in,
                              void* d_out, int out_size)
{
    const float* query   = (const float*)d_in[0];
    const float* context = (const float*)d_in[1];
    const float* Wq      = (const float*)d_in[2];
    const float* bq      = (const float*)d_in[3];
    const float* Wc      = (const float*)d_in[4];
    const float* bc      = (const float*)d_in[5];
    const float* Wv      = (const float*)d_in[6];
    // d_in[7] = bv : constant pre-softmax shift, mathematically a no-op.

    wt_kernel    <<<dim3(64, 2), 256>>>(Wq, Wc);
    proj_kernel  <<<256, 256>>>(query, context, bq, bc);
    scores_kernel<<<1024, 256>>>(Wv);
    out_kernel   <<<256, 256>>>(context, (float*)d_out);
}

// round 8
// speedup vs baseline: 1.5444x; 1.5444x over previous
#include <cuda_runtime.h>
#include <cuda_fp16.h>
#include <cstdint>

#define B_  4
#define LQ  512
#define LK  512
#define DQ  256
#define DC  256
#define H_  128

typedef unsigned long long ull;

// Scratch (__device__ globals: allocation-free rule)
__device__ float g_qp  [B_ * LQ * H_];        // [row][h] : query proj + bq
__device__ float g_c2T [B_ * H_ * LK];        // [b][h][k]: 2*(ctx proj + bc)
__device__ float g_attn[B_ * LQ * LK];        // softmax weights
__device__ ull   g_WT2 [2][DQ / 2][H_];       // [m][d2][h] packed W columns

// ---------- f32x2 helpers ----------
__device__ __forceinline__ ull pk(float a, float b) {
    ull r; asm("mov.b64 %0, {%1, %2};" : "=l"(r) : "f"(a), "f"(b)); return r;
}
__device__ __forceinline__ void upk(ull v, float& a, float& b) {
    asm("mov.b64 {%0, %1}, %2;" : "=f"(a), "=f"(b) : "l"(v));
}
__device__ __forceinline__ ull add2(ull a, ull b) {
    ull r; asm("add.rn.f32x2 %0, %1, %2;" : "=l"(r) : "l"(a), "l"(b)); return r;
}
__device__ __forceinline__ ull fma2(ull a, ull b, ull c) {
    ull r; asm("fma.rn.f32x2 %0, %1, %2, %3;" : "=l"(r) : "l"(a), "l"(b), "l"(c)); return r;
}
__device__ __forceinline__ __half2 tanh2(__half2 v) {
    uint32_t x = *reinterpret_cast<uint32_t*>(&v), y;
    asm("tanh.approx.f16x2 %0, %1;" : "=r"(y) : "r"(x));
    return *reinterpret_cast<__half2*>(&y);
}

// ---------------------------------------------------------------------------
// Kernel 0: pack-transpose W -> g_WT2[m][d2][h]
// ---------------------------------------------------------------------------
__global__ __launch_bounds__(256) void wt_kernel(
    const float* __restrict__ Wq, const float* __restrict__ Wc)
{
    const int m = blockIdx.y;
    const float* W = m ? Wc : Wq;
    const int idx = blockIdx.x * 256 + threadIdx.x;
    const int d2 = idx >> 7, h = idx & 127;
    g_WT2[m][d2][h] = pk(W[h * DQ + 2 * d2], W[h * DQ + 2 * d2 + 1]);
}

// ---------------------------------------------------------------------------
// Kernel 1: projections (R3-proven), float outputs.
// ---------------------------------------------------------------------------
__global__ __launch_bounds__(256) void proj_kernel(
    const float* __restrict__ query, const float* __restrict__ context,
    const float* __restrict__ bq, const float* __restrict__ bc)
{
    __shared__ float insh[16][256];

    const int m    = blockIdx.x >> 7;
    const int tile = blockIdx.x & 127;
    const float* in   = m ? context : query;
    const float* bias = m ? bc : bq;
    const int t  = threadIdx.x;
    const int r0 = tile * 16;

    {
        const float4* src = (const float4*)(in + (size_t)r0 * 256);
        float4* dst = (float4*)insh;
        #pragma unroll
        for (int i = t; i < 16 * 64; i += 256) dst[i] = src[i];
    }
    __syncthreads();

    const int h  = t & 127;
    const int rg = t >> 7;
    const float bb = bias[h];
    ull acc[8];
    #pragma unroll
    for (int j = 0; j < 8; j++) acc[j] = pk(bb, 0.0f);

    const ull* wp = &g_WT2[m][0][h];
    #pragma unroll 4
    for (int d4 = 0; d4 < 64; d4++) {
        const ull w01 = wp[(2 * d4)     * H_];
        const ull w23 = wp[(2 * d4 + 1) * H_];
        #pragma unroll
        for (int j = 0; j < 8; j++) {
            const ulonglong2 q2 = *(const ulonglong2*)&insh[rg * 8 + j][d4 * 4];
            acc[j] = fma2(w01, q2.x, acc[j]);
            acc[j] = fma2(w23, q2.y, acc[j]);
        }
    }

    #pragma unroll
    for (int j = 0; j < 8; j++) {
        float lo, hi; upk(acc[j], lo, hi);
        const float s = lo + hi;
        const int row = r0 + rg * 8 + j;
        if (m == 0) {
            g_qp[(size_t)row * H_ + h] = s;
        } else {
            const int b = row >> 9, k = row & 511;
            g_c2T[((size_t)b * H_ + h) * LK + k] = 2.0f * s;
        }
    }
}

// ---------------------------------------------------------------------------
// Kernel 2: scores + softmax. R3 structure (256 CTAs, 8q/CTA, f32 LDG.128),
// NEW inner loop: c packed to half2 once per k-pair (shared across 4 q),
// then HADD2 + tanh2 + HFMA2 into fp16 window accumulators, flushed to
// f32x2 every 4 h. ~2.6x fewer instructions, identical memory pattern.
// ---------------------------------------------------------------------------
__global__ __launch_bounds__(256) void scores_kernel(const float* __restrict__ Wv)
{
    __shared__ __half2 qsh[8][H_];    // (qp, qp) half2 per (q, h)
    __shared__ __half2 wvh[H_];       // (Wv, Wv) half2
    __shared__ float   sc[8][LK];     // scores

    const int tile = blockIdx.x;          // 0..255
    const int b  = tile >> 6;
    const int q0 = (tile & 63) * 8;
    const int t  = threadIdx.x;

    #pragma unroll
    for (int i = t; i < 8 * H_; i += 256) {
        const int q = i >> 7, h = i & 127;
        const float v = g_qp[((size_t)(b * LQ + q0 + q)) * H_ + h];
        qsh[q][h] = __float2half2_rn(v);
    }
    if (t < H_) wvh[t] = __float2half2_rn(Wv[t]);
    __syncthreads();

    const int kt = t & 127;               // float4 chunk of k
    const int qg = (t >> 7) * 4;          // q-offset 0 or 4
    const ulonglong2* cp =
        (const ulonglong2*)(g_c2T + (size_t)b * H_ * LK) + kt;

    const __half2 hz = __floats2half2_rn(0.0f, 0.0f);

    ull facc[4][2];
    __half2 wacc[4][2];
    #pragma unroll
    for (int qi = 0; qi < 4; qi++) {
        facc[qi][0] = 0ULL; facc[qi][1] = 0ULL;
        wacc[qi][0] = hz;   wacc[qi][1] = hz;
    }

    #pragma unroll 1
    for (int hw = 0; hw < 32; hw++) {     // 32 windows of 4 h
        #pragma unroll
        for (int j = 0; j < 4; j++) {
            const int h = hw * 4 + j;
            const ulonglong2 cc = cp[(size_t)h * 128];  // LDG.128 coalesced
            float a0, a1, a2, a3;
            upk(cc.x, a0, a1); upk(cc.y, a2, a3);
            const __half2 c01 = __floats2half2_rn(a0, a1);  // shared across q
            const __half2 c23 = __floats2half2_rn(a2, a3);
            const __half2 wv = wvh[h];                       // broadcast
            #pragma unroll
            for (int qi = 0; qi < 4; qi++) {
                const __half2 qq = qsh[qg + qi][h];          // broadcast
                wacc[qi][0] = __hfma2(tanh2(__hadd2(qq, c01)), wv, wacc[qi][0]);
                wacc[qi][1] = __hfma2(tanh2(__hadd2(qq, c23)), wv, wacc[qi][1]);
            }
        }
        // flush fp16 window -> f32x2 accumulators
        #pragma unroll
        for (int qi = 0; qi < 4; qi++) {
            #pragma unroll
            for (int p = 0; p < 2; p++) {
                const float2 f = __half22float2(wacc[qi][p]);
                facc[qi][p] = add2(pk(f.x, f.y), facc[qi][p]);
                wacc[qi][p] = hz;
            }
        }
    }

    #pragma unroll
    for (int qi = 0; qi < 4; qi++) {
        float s0, s1, s2, s3;
        upk(facc[qi][0], s0, s1);
        upk(facc[qi][1], s2, s3);
        *(float4*)&sc[qg + qi][kt * 4] = make_float4(s0, s1, s2, s3);
    }
    __syncthreads();

    // softmax: warp w handles q = q0 + w
    const int w = t >> 5, lane = t & 31;
    float e[16];
    float mx = -1e30f;
    #pragma unroll
    for (int j = 0; j < 16; j++) {
        e[j] = sc[w][lane + j * 32];
        mx = fmaxf(mx, e[j]);
    }
    #pragma unroll
    for (int off = 16; off > 0; off >>= 1)
        mx = fmaxf(mx, __shfl_xor_sync(0xffffffffu, mx, off));
    float s = 0.0f;
    #pragma unroll
    for (int j = 0; j < 16; j++) { e[j] = __expf(e[j] - mx); s += e[j]; }
    #pragma unroll
    for (int off = 16; off > 0; off >>= 1)
        s += __shfl_xor_sync(0xffffffffu, s, off);
    const float inv = 1.0f / s;
    float* dst = g_attn + ((size_t)b * LQ + q0 + w) * LK;
    #pragma unroll
    for (int j = 0; j < 16; j++) dst[lane + j * 32] = e[j] * inv;
}

// ---------------------------------------------------------------------------
// Kernel 3: out = attn @ context — R3 smem GEMM (BM=64, BN=64, BK=32,
// 128 CTAs), now DOUBLE-BUFFERED: one __syncthreads per stage, prefetch
// issued before compute so LDG latency fully overlaps the k-loop.
// ---------------------------------------------------------------------------
__global__ __launch_bounds__(256) void out_kernel(
    const float* __restrict__ context, float* __restrict__ out)
{
    __shared__ float a_sh[2][32][68];    // [buf][k][q] transposed attn tile
    __shared__ float c_sh[2][32][68];    // [buf][k][d] ctx tile

    const int bx = blockIdx.x;        // 0..127
    const int b  = bx >> 5;
    const int q0 = ((bx >> 2) & 7) * 64;
    const int d0 = (bx & 3) * 64;
    const int t  = threadIdx.x;
    const int tx = t & 15;            // d-group: d0 + tx*4
    const int ty = t >> 4;            // q-group: q0 + ty*4

    const int ar = t >> 3, ac4 = t & 7;     // attn: rows ar, ar+32
    const int cr = t >> 4, cc4 = t & 15;    // ctx:  rows cr, cr+16

    const float4* ag = (const float4*)(g_attn + ((size_t)b * LQ + q0) * LK);
    const float4* cg = (const float4*)(context + (size_t)b * LK * DC + d0);

    // stage 0 -> buffer 0
    {
        float4 pa0 = ag[(size_t)ar * 128 + ac4];
        float4 pa1 = ag[(size_t)(ar + 32) * 128 + ac4];
        float4 pc0 = cg[(size_t)cr * 64 + cc4];
        float4 pc1 = cg[(size_t)(cr + 16) * 64 + cc4];
        a_sh[0][ac4 * 4 + 0][ar] = pa0.x;
        a_sh[0][ac4 * 4 + 1][ar] = pa0.y;
        a_sh[0][ac4 * 4 + 2][ar] = pa0.z;
        a_sh[0][ac4 * 4 + 3][ar] = pa0.w;
        a_sh[0][ac4 * 4 + 0][ar + 32] = pa1.x;
        a_sh[0][ac4 * 4 + 1][ar + 32] = pa1.y;
        a_sh[0][ac4 * 4 + 2][ar + 32] = pa1.z;
        a_sh[0][ac4 * 4 + 3][ar + 32] = pa1.w;
        *(float4*)&c_sh[0][cr][cc4 * 4]      = pc0;
        *(float4*)&c_sh[0][cr + 16][cc4 * 4] = pc1;
    }
    __syncthreads();

    ull acc[2][4];
    #pragma unroll
    for (int p = 0; p < 2; p++)
        #pragma unroll
        for (int d = 0; d < 4; d++) acc[p][d] = 0ULL;

    #pragma unroll 1
    for (int s = 0; s < 16; s++) {
        const int cur = s & 1, nxt = cur ^ 1;

        float4 pa0, pa1, pc0, pc1;
        if (s < 15) {   // issue next-stage loads BEFORE compute
            const int k4 = (s + 1) * 8;
            const int kr = (s + 1) * 32;
            pa0 = ag[(size_t)ar * 128 + k4 + ac4];
            pa1 = ag[(size_t)(ar + 32) * 128 + k4 + ac4];
            pc0 = cg[(size_t)(kr + cr) * 64 + cc4];
            pc1 = cg[(size_t)(kr + cr + 16) * 64 + cc4];
        }

        #pragma unroll
        for (int k = 0; k < 32; k++) {
            const ulonglong2 a2 = *(const ulonglong2*)&a_sh[cur][k][ty * 4];
            const float4 c4 = *(const float4*)&c_sh[cur][k][tx * 4];
            const ull cx = pk(c4.x, c4.x);
            const ull cy = pk(c4.y, c4.y);
            const ull cz = pk(c4.z, c4.z);
            const ull cw = pk(c4.w, c4.w);
            acc[0][0] = fma2(a2.x, cx, acc[0][0]);
            acc[0][1] = fma2(a2.x, cy, acc[0][1]);
            acc[0][2] = fma2(a2.x, cz, acc[0][2]);
            acc[0][3] = fma2(a2.x, cw, acc[0][3]);
            acc[1][0] = fma2(a2.y, cx, acc[1][0]);
            acc[1][1] = fma2(a2.y, cy, acc[1][1]);
            acc[1][2] = fma2(a2.y, cz, acc[1][2]);
            acc[1][3] = fma2(a2.y, cw, acc[1][3]);
        }

        if (s < 15) {
            a_sh[nxt][ac4 * 4 + 0][ar] = pa0.x;
            a_sh[nxt][ac4 * 4 + 1][ar] = pa0.y;
            a_sh[nxt][ac4 * 4 + 2][ar] = pa0.z;
            a_sh[nxt][ac4 * 4 + 3][ar] = pa0.w;
            a_sh[nxt][ac4 * 4 + 0][ar + 32] = pa1.x;
            a_sh[nxt][ac4 * 4 + 1][ar + 32] = pa1.y;
            a_sh[nxt][ac4 * 4 + 2][ar + 32] = pa1.z;
            a_sh[nxt][ac4 * 4 + 3][ar + 32] = pa1.w;
            *(float4*)&c_sh[nxt][cr][cc4 * 4]      = pc0;
            *(float4*)&c_sh[nxt][cr + 16][cc4 * 4] = pc1;
            __syncthreads();
        }
    }

    float o[4][4];
    #pragma unroll
    for (int p = 0; p < 2; p++)
        #pragma unroll
        for (int d = 0; d < 4; d++)
            upk(acc[p][d], o[2 * p][d], o[2 * p + 1][d]);

    #pragma unroll
    for (int qi = 0; qi < 4; qi++) {
        float4* dst = (float4*)(out + ((size_t)b * LQ + q0 + ty * 4 + qi) * DC
                                + d0 + tx * 4);
        *dst = make_float4(o[qi][0], o[qi][1], o[qi][2], o[qi][3]);
    }
}

// ---------------------------------------------------------------------------
extern "C" void kernel_launch(void* const* d_in, const int* in_sizes, int n_in,
                              void* d_out, int out_size)
{
    const float* query   = (const float*)d_in[0];
    const float* context = (const float*)d_in[1];
    const float* Wq      = (const float*)d_in[2];
    const float* bq      = (const float*)d_in[3];
    const float* Wc      = (const float*)d_in[4];
    const float* bc      = (const float*)d_in[5];
    const float* Wv      = (const float*)d_in[6];
    // d_in[7] = bv : constant pre-softmax shift, mathematically a no-op.

    wt_kernel    <<<dim3(64, 2), 256>>>(Wq, Wc);
    proj_kernel  <<<256, 256>>>(query, context, bq, bc);
    scores_kernel<<<256, 256>>>(Wv);
    out_kernel   <<<128, 256>>>(context, (float*)d_out);
}